// round 1
// baseline (speedup 1.0000x reference)
#include <cuda_runtime.h>
#include <math.h>

#define BB 32
#define SS 1024
#define CC 384
#define HH 384
#define MAX_OUT_T 3072
#define M_TOTAL (BB*SS)          // 32768
#define KDIM (3*CC)              // 1152
#define PRED_OFFSET ((size_t)BB*MAX_OUT_T*CC)  // 37748736

// Scratch (static device globals: allocation-free)
__device__ float g_tmp1[(size_t)M_TOTAL*HH];
__device__ float g_tmp2[(size_t)M_TOTAL*HH];
__device__ int   g_cum[BB*SS];

// ---------------------------------------------------------------------------
// Conv-as-GEMM: out[m, n] = sum_{kc} A[m, kc] * W[kc, n] + bias[n]
//   A[m, kc] (implicit im2col): k = kc/CC, c = kc%CC, s = m%SS,
//   value = (0 <= s+k-1 < SS) ? in[(m+k-1)*CC + c] : 0
// Tile: TM=64, TN=128, TK=16. 256 threads, 4x8 micro-tile per thread.
// ---------------------------------------------------------------------------
#define TM 64
#define TN 128
#define TK 16

__global__ __launch_bounds__(256)
void conv_gemm(const float* __restrict__ A, const float* __restrict__ W,
               const float* __restrict__ bias, float* __restrict__ out)
{
    __shared__ float As[TK][TM + 4];   // row length 68 floats (16B-aligned, de-conflicted)
    __shared__ float Bs[TK][TN];

    const int tid = threadIdx.x;
    const int tx = tid & 15;           // 0..15 -> 8 output cols each
    const int ty = tid >> 4;           // 0..15 -> 4 output rows each
    const int m0 = blockIdx.y * TM;
    const int n0 = blockIdx.x * TN;

    float acc[4][8];
#pragma unroll
    for (int i = 0; i < 4; i++)
#pragma unroll
        for (int j = 0; j < 8; j++) acc[i][j] = 0.f;

    // A-load assignment: thread -> (row ar, 4-wide kc chunk aq)
    const int ar = tid >> 2;           // 0..63
    const int aq = (tid & 3) * 4;      // 0,4,8,12
    const int m  = m0 + ar;
    const int s  = m & (SS - 1);

    for (int kc0 = 0; kc0 < KDIM; kc0 += TK) {
        // --- load A tile (implicit im2col, zero halo at sequence edges) ---
        {
            const int kc = kc0 + aq;
            const int k  = kc / CC;
            const int c  = kc - k * CC;      // multiple of 4; never crosses k boundary
            const int ss = s + k - 1;
            float4 av = make_float4(0.f, 0.f, 0.f, 0.f);
            if (ss >= 0 && ss < SS)
                av = *(const float4*)(A + (size_t)(m + k - 1) * CC + c);
            As[aq + 0][ar] = av.x;
            As[aq + 1][ar] = av.y;
            As[aq + 2][ar] = av.z;
            As[aq + 3][ar] = av.w;
        }
        // --- load B tile: 16 x 128, coalesced float4 ---
#pragma unroll
        for (int it = 0; it < 2; it++) {
            const int fidx = it * 256 + tid;
            const int brow = fidx >> 5;         // 0..15
            const int bc   = (fidx & 31) * 4;   // 0..124 step 4
            *(float4*)&Bs[brow][bc] =
                *(const float4*)(W + (size_t)(kc0 + brow) * HH + n0 + bc);
        }
        __syncthreads();

#pragma unroll
        for (int kk = 0; kk < TK; kk++) {
            float4 a  = *(const float4*)&As[kk][ty * 4];
            float4 b0 = *(const float4*)&Bs[kk][tx * 8];
            float4 b1 = *(const float4*)&Bs[kk][tx * 8 + 4];
            float av[4] = {a.x, a.y, a.z, a.w};
            float bv[8] = {b0.x, b0.y, b0.z, b0.w, b1.x, b1.y, b1.z, b1.w};
#pragma unroll
            for (int i = 0; i < 4; i++)
#pragma unroll
                for (int j = 0; j < 8; j++)
                    acc[i][j] = fmaf(av[i], bv[j], acc[i][j]);
        }
        __syncthreads();
    }

    // --- epilogue: bias add, vectorized store ---
    const int ncol = n0 + tx * 8;
    float4 bia0 = *(const float4*)(bias + ncol);
    float4 bia1 = *(const float4*)(bias + ncol + 4);
#pragma unroll
    for (int i = 0; i < 4; i++) {
        const int row = m0 + ty * 4 + i;
        float4 o0 = make_float4(acc[i][0] + bia0.x, acc[i][1] + bia0.y,
                                acc[i][2] + bia0.z, acc[i][3] + bia0.w);
        float4 o1 = make_float4(acc[i][4] + bia1.x, acc[i][5] + bia1.y,
                                acc[i][6] + bia1.z, acc[i][7] + bia1.w);
        *(float4*)(out + (size_t)row * HH + ncol)     = o0;
        *(float4*)(out + (size_t)row * HH + ncol + 4) = o1;
    }
}

// ---------------------------------------------------------------------------
// In-place LayerNorm (population var) + ReLU over last dim (384). 1 block/row.
// ---------------------------------------------------------------------------
__global__ __launch_bounds__(128)
void ln_relu(float* __restrict__ data, const float* __restrict__ g,
             const float* __restrict__ beta)
{
    const int row = blockIdx.x;
    const int tid = threadIdx.x;
    float* p = data + (size_t)row * HH;

    float v0 = p[tid];
    float v1 = p[tid + 128];
    float v2 = p[tid + 256];
    float s  = v0 + v1 + v2;
    float sq = v0 * v0 + v1 * v1 + v2 * v2;

    // warp reduce
#pragma unroll
    for (int off = 16; off > 0; off >>= 1) {
        s  += __shfl_down_sync(0xffffffffu, s,  off);
        sq += __shfl_down_sync(0xffffffffu, sq, off);
    }
    __shared__ float red_s[4], red_q[4];
    const int wid = tid >> 5, lane = tid & 31;
    if (lane == 0) { red_s[wid] = s; red_q[wid] = sq; }
    __syncthreads();
    __shared__ float sh_mu, sh_rs;
    if (tid == 0) {
        float ts = red_s[0] + red_s[1] + red_s[2] + red_s[3];
        float tq = red_q[0] + red_q[1] + red_q[2] + red_q[3];
        float mu = ts * (1.f / HH);
        float var = tq * (1.f / HH) - mu * mu;
        sh_mu = mu;
        sh_rs = rsqrtf(var + 1e-5f);
    }
    __syncthreads();
    const float mu = sh_mu, rs = sh_rs;

    p[tid]       = fmaxf(0.f, (v0 - mu) * rs * g[tid]       + beta[tid]);
    p[tid + 128] = fmaxf(0.f, (v1 - mu) * rs * g[tid + 128] + beta[tid + 128]);
    p[tid + 256] = fmaxf(0.f, (v2 - mu) * rs * g[tid + 256] + beta[tid + 256]);
}

// ---------------------------------------------------------------------------
// pred_dur[m] = exp(dot(h[m,:], wl) + bl). One warp per row.
// ---------------------------------------------------------------------------
__global__ __launch_bounds__(256)
void linear_exp(const float* __restrict__ h, const float* __restrict__ wl,
                const float* __restrict__ bl, float* __restrict__ pred)
{
    const int gw   = (blockIdx.x * 256 + threadIdx.x) >> 5;  // global warp = row
    const int lane = threadIdx.x & 31;
    if (gw >= M_TOTAL) return;

    const float4* hp = (const float4*)(h + (size_t)gw * HH);
    const float4* wp = (const float4*)wl;
    float sum = 0.f;
#pragma unroll
    for (int i = 0; i < 3; i++) {
        float4 hv = hp[lane + i * 32];
        float4 wv = wp[lane + i * 32];
        sum += hv.x * wv.x + hv.y * wv.y + hv.z * wv.z + hv.w * wv.w;
    }
#pragma unroll
    for (int off = 16; off > 0; off >>= 1)
        sum += __shfl_down_sync(0xffffffffu, sum, off);
    if (lane == 0) pred[gw] = expf(sum + bl[0]);
}

// ---------------------------------------------------------------------------
// Per-batch inclusive cumsum of durations (Hillis-Steele, 1024 threads).
// ---------------------------------------------------------------------------
__global__ __launch_bounds__(1024)
void cumsum_kernel(const int* __restrict__ dur, int* __restrict__ cum)
{
    __shared__ int buf[SS];
    const int b = blockIdx.x, tid = threadIdx.x;
    buf[tid] = dur[b * SS + tid];
    __syncthreads();
#pragma unroll
    for (int off = 1; off < SS; off <<= 1) {
        int t = buf[tid];
        int u = (tid >= off) ? buf[tid - off] : 0;
        __syncthreads();
        buf[tid] = t + u;
        __syncthreads();
    }
    cum[b * SS + tid] = buf[tid];
}

// ---------------------------------------------------------------------------
// Length regulation gather. One warp per output row (b, t):
//   src = upper_bound(cum[b,:], t), clipped; res = valid ? x[b,src,:] : 0
// ---------------------------------------------------------------------------
__global__ __launch_bounds__(256)
void gather_kernel(const float* __restrict__ x, const int* __restrict__ cum,
                   float* __restrict__ out)
{
    const int gw   = (blockIdx.x * 256 + threadIdx.x) >> 5;   // 0 .. B*MAX_OUT-1
    const int lane = threadIdx.x & 31;
    const int b = gw / MAX_OUT_T;
    const int t = gw - b * MAX_OUT_T;

    const int* c = cum + b * SS;
    const bool valid = t < c[SS - 1];
    int lo = 0, hi = SS;
    while (lo < hi) {
        int mid = (lo + hi) >> 1;
        if (c[mid] <= t) lo = mid + 1; else hi = mid;
    }
    const int src = min(lo, SS - 1);

    const float4* xin = (const float4*)(x + ((size_t)b * SS + src) * CC);
    float4* o = (float4*)(out + (size_t)gw * CC);
    const float4 z = make_float4(0.f, 0.f, 0.f, 0.f);
#pragma unroll
    for (int i = 0; i < 3; i++)
        o[lane + i * 32] = valid ? xin[lane + i * 32] : z;
}

// ---------------------------------------------------------------------------
extern "C" void kernel_launch(void* const* d_in, const int* in_sizes, int n_in,
                              void* d_out, int out_size)
{
    const float* x     = (const float*)d_in[0];
    const int*   dur   = (const int*)  d_in[1];
    const float* w1    = (const float*)d_in[2];
    const float* b1    = (const float*)d_in[3];
    const float* g1    = (const float*)d_in[4];
    const float* beta1 = (const float*)d_in[5];
    const float* w2    = (const float*)d_in[6];
    const float* b2    = (const float*)d_in[7];
    const float* g2    = (const float*)d_in[8];
    const float* beta2 = (const float*)d_in[9];
    const float* wl    = (const float*)d_in[10];
    const float* bl    = (const float*)d_in[11];
    float* out = (float*)d_out;

    float *tmp1, *tmp2; int* cum;
    cudaGetSymbolAddress((void**)&tmp1, g_tmp1);
    cudaGetSymbolAddress((void**)&tmp2, g_tmp2);
    cudaGetSymbolAddress((void**)&cum,  g_cum);

    dim3 gemm_grid(HH / TN, M_TOTAL / TM);   // (3, 512)
    dim3 gemm_block(256);

    // Duration predictor
    conv_gemm<<<gemm_grid, gemm_block>>>(x, w1, b1, tmp1);
    ln_relu<<<M_TOTAL, 128>>>(tmp1, g1, beta1);
    conv_gemm<<<gemm_grid, gemm_block>>>(tmp1, w2, b2, tmp2);
    ln_relu<<<M_TOTAL, 128>>>(tmp2, g2, beta2);
    linear_exp<<<M_TOTAL / 8, 256>>>(tmp2, wl, bl, out + PRED_OFFSET);

    // Length regulation
    cumsum_kernel<<<BB, SS>>>(dur, cum);
    gather_kernel<<<(BB * MAX_OUT_T) / 8, 256>>>(x, cum, out);
}

// round 3
// speedup vs baseline: 9.1211x; 9.1211x over previous
#include <cuda_runtime.h>
#include <cuda_bf16.h>
#include <math.h>
#include <stdint.h>

#define BB 32
#define SS 1024
#define CC 384
#define HH 384
#define MAX_OUT_T 3072
#define M_TOTAL (BB*SS)          // 32768
#define KDIM (3*CC)              // 1152
#define PRED_OFFSET ((size_t)BB*MAX_OUT_T*CC)

// ---------------- scratch (static device globals: allocation-free) ----------
__device__ __nv_bfloat16 g_xb [(size_t)M_TOTAL*CC];
__device__ __nv_bfloat16 g_h1b[(size_t)M_TOTAL*HH];
__device__ __nv_bfloat16 g_wt1[(size_t)HH*KDIM];
__device__ __nv_bfloat16 g_wt2[(size_t)HH*KDIM];
__device__ float g_tmp1[(size_t)M_TOTAL*HH];
__device__ float g_tmp2[(size_t)M_TOTAL*HH];
__device__ int   g_cum[BB*SS];

// ---------------- PTX helpers (baseline PTX only: sm_80-era ops) ------------
__device__ __forceinline__ uint32_t smem_u32(const void* p) {
    uint32_t a;
    asm("{ .reg .u64 t; cvta.to.shared.u64 t, %1; cvt.u32.u64 %0, t; }" : "=r"(a) : "l"(p));
    return a;
}
__device__ __forceinline__ void cp_async16(uint32_t saddr, const void* gptr, uint32_t sz) {
    asm volatile("cp.async.ca.shared.global [%0], [%1], 16, %2;"
                 :: "r"(saddr), "l"(gptr), "r"(sz) : "memory");
}
__device__ __forceinline__ void cp_commit() {
    asm volatile("cp.async.commit_group;" ::: "memory");
}
template <int N>
__device__ __forceinline__ void cp_wait() {
    asm volatile("cp.async.wait_group %0;" :: "n"(N) : "memory");
}
__device__ __forceinline__ void ldmatrix_x4(uint32_t& r0, uint32_t& r1, uint32_t& r2,
                                            uint32_t& r3, uint32_t addr) {
    asm volatile("ldmatrix.sync.aligned.m8n8.x4.shared.b16 {%0,%1,%2,%3}, [%4];"
                 : "=r"(r0), "=r"(r1), "=r"(r2), "=r"(r3) : "r"(addr));
}
__device__ __forceinline__ void mma_16816(float& d0, float& d1, float& d2, float& d3,
                                          uint32_t a0, uint32_t a1, uint32_t a2, uint32_t a3,
                                          uint32_t b0, uint32_t b1) {
    asm volatile("mma.sync.aligned.m16n8k16.row.col.f32.bf16.bf16.f32 "
                 "{%0,%1,%2,%3}, {%4,%5,%6,%7}, {%8,%9}, {%0,%1,%2,%3};"
                 : "+f"(d0), "+f"(d1), "+f"(d2), "+f"(d3)
                 : "r"(a0), "r"(a1), "r"(a2), "r"(a3), "r"(b0), "r"(b1));
}

// ---------------------------------------------------------------------------
// Conv-as-GEMM on tensor cores (mma.sync bf16):
//   out[m,n] = sum_kc A_im2col[m,kc] * Wt[n,kc] + bias[n]
// CTA tile 128x128; 8 warps as 2(m) x 4(n); warp tile 64x32.
// K = 1152 in 18 chunks of 64 bf16; cp.async double-buffered smem, SW128.
// ---------------------------------------------------------------------------
#define NSTEPS 18
#define TILE_B 16384                       // 128 rows x 128 bytes
#define GEMM_SMEM (4*TILE_B)               // A0 A1 B0 B1

__global__ __launch_bounds__(256, 1)
void conv_gemm_mma(const __nv_bfloat16* __restrict__ A,
                   const __nv_bfloat16* __restrict__ Wt,
                   const float* __restrict__ bias,
                   float* __restrict__ out)
{
    extern __shared__ __align__(1024) char smem[];
    const uint32_t sbase = smem_u32(smem);
    const int tid  = threadIdx.x;
    const int wid  = tid >> 5;
    const int lane = tid & 31;
    const int warp_m = wid & 1;            // 0..1 -> 64-row halves
    const int warp_n = wid >> 1;           // 0..3 -> 32-col quarters
    const int n0 = blockIdx.x * 128;
    const int m0 = blockIdx.y * 128;

    const uint32_t aoff[2] = { 0u,        TILE_B };
    const uint32_t boff[2] = { 2*TILE_B,  3*TILE_B };

    // per-thread load geometry (4 segments of 16B per tile per thread)
    const int lrow = tid >> 3;              // 0..31 (+32*i)
    const int lcx  = (tid & 7) * 16;        // byte offset within 128B row

    // ---- tile loaders -------------------------------------------------------
    auto load_A = [&](int step, int buf) {
        const int k  = step / 6;
        const int c0 = (step - k * 6) * 64;
#pragma unroll
        for (int i = 0; i < 4; i++) {
            const int row = lrow + 32 * i;
            const int gm  = m0 + row;
            const int ss  = (gm & (SS - 1)) + k - 1;
            const bool valid = (ss >= 0) && (ss < SS);
            const char* gp = (const char*)A + ((size_t)(gm + k - 1) * CC + c0) * 2 + lcx;
            if (!valid) gp = (const char*)A;          // safe dummy, sz=0 below
            uint32_t off = (uint32_t)(row * 128 + lcx);
            uint32_t sw  = off ^ ((off >> 3) & 0x70);
            cp_async16(sbase + aoff[buf] + sw, gp, valid ? 16u : 0u);
        }
    };
    auto load_B = [&](int step, int buf) {
#pragma unroll
        for (int i = 0; i < 4; i++) {
            const int row = lrow + 32 * i;
            const char* gp = (const char*)Wt + ((size_t)(n0 + row) * KDIM + step * 64) * 2 + lcx;
            uint32_t off = (uint32_t)(row * 128 + lcx);
            uint32_t sw  = off ^ ((off >> 3) & 0x70);
            cp_async16(sbase + boff[buf] + sw, gp, 16u);
        }
    };

    float acc[4][4][4];
#pragma unroll
    for (int i = 0; i < 4; i++)
#pragma unroll
        for (int j = 0; j < 4; j++)
#pragma unroll
            for (int q = 0; q < 4; q++) acc[i][j][q] = 0.f;

    // ldmatrix lane addressing (same pattern for A and B fragments)
    const int fr_row = ((lane >> 3) & 1) * 8 + (lane & 7);  // row within 16-row frag
    const int fr_kb  = (lane >> 4) * 16;                    // 0 or 16 bytes (k 0/8)

    // ---- prologue: prefetch chunks 0 and 1 ---------------------------------
    load_A(0, 0); load_B(0, 0); cp_commit();
    load_A(1, 1); load_B(1, 1); cp_commit();

    for (int step = 0; step < NSTEPS; ++step) {
        const int buf = step & 1;
        if (step < NSTEPS - 2) cp_wait<1>(); else cp_wait<0>();
        __syncthreads();

        const uint32_t sa = sbase + aoff[buf];
        const uint32_t sb = sbase + boff[buf];

#pragma unroll
        for (int ks = 0; ks < 4; ks++) {                 // 4 x k16 within chunk
            uint32_t a[4][4];
#pragma unroll
            for (int mt = 0; mt < 4; mt++) {
                const int row = warp_m * 64 + mt * 16 + fr_row;
                uint32_t off = (uint32_t)(row * 128 + ks * 32 + fr_kb);
                uint32_t sw  = off ^ ((off >> 3) & 0x70);
                ldmatrix_x4(a[mt][0], a[mt][1], a[mt][2], a[mt][3], sa + sw);
            }
            uint32_t b[2][4];
#pragma unroll
            for (int nt = 0; nt < 2; nt++) {
                const int row = warp_n * 32 + nt * 16 + fr_row;
                uint32_t off = (uint32_t)(row * 128 + ks * 32 + fr_kb);
                uint32_t sw  = off ^ ((off >> 3) & 0x70);
                ldmatrix_x4(b[nt][0], b[nt][1], b[nt][2], b[nt][3], sb + sw);
            }
#pragma unroll
            for (int mt = 0; mt < 4; mt++)
#pragma unroll
                for (int nt = 0; nt < 2; nt++)
#pragma unroll
                    for (int h = 0; h < 2; h++) {
                        const int j = nt * 2 + h;
                        mma_16816(acc[mt][j][0], acc[mt][j][1], acc[mt][j][2], acc[mt][j][3],
                                  a[mt][0], a[mt][1], a[mt][2], a[mt][3],
                                  b[nt][h], b[nt][2 + h]);
                    }
        }
        __syncthreads();
        if (step + 2 < NSTEPS) {
            load_A(step + 2, buf); load_B(step + 2, buf);
            cp_commit();
        }
    }

    // ---- epilogue: bias add, float2 stores ---------------------------------
    const int g = lane >> 2;
    const int t = lane & 3;
#pragma unroll
    for (int mt = 0; mt < 4; mt++) {
        const int row0 = m0 + warp_m * 64 + mt * 16 + g;
#pragma unroll
        for (int j = 0; j < 4; j++) {
            const int col = n0 + warp_n * 32 + j * 8 + t * 2;
            const float2 bv = *(const float2*)(bias + col);
            float2 o0 = make_float2(acc[mt][j][0] + bv.x, acc[mt][j][1] + bv.y);
            float2 o1 = make_float2(acc[mt][j][2] + bv.x, acc[mt][j][3] + bv.y);
            *(float2*)(out + (size_t)row0 * HH + col)       = o0;
            *(float2*)(out + (size_t)(row0 + 8) * HH + col) = o1;
        }
    }
}

// ---------------------------------------------------------------------------
// LayerNorm + ReLU -> bf16 output (for conv2 input). 192 thr, 2 elems/thread.
// ---------------------------------------------------------------------------
__global__ __launch_bounds__(192)
void ln_relu_bf16(const float* __restrict__ in, const float* __restrict__ g,
                  const float* __restrict__ beta, __nv_bfloat16* __restrict__ outb)
{
    const int row = blockIdx.x, tid = threadIdx.x;
    const float2 v = *(const float2*)(in + (size_t)row * HH + tid * 2);
    float s = v.x + v.y, sq = v.x * v.x + v.y * v.y;
#pragma unroll
    for (int off = 16; off > 0; off >>= 1) {
        s  += __shfl_down_sync(0xffffffffu, s,  off);
        sq += __shfl_down_sync(0xffffffffu, sq, off);
    }
    __shared__ float rs_[6], rq_[6];
    const int wd = tid >> 5, ln = tid & 31;
    if (ln == 0) { rs_[wd] = s; rq_[wd] = sq; }
    __syncthreads();
    __shared__ float sh_mu, sh_rs;
    if (tid == 0) {
        float ts = 0.f, tq = 0.f;
#pragma unroll
        for (int i = 0; i < 6; i++) { ts += rs_[i]; tq += rq_[i]; }
        float mu = ts * (1.f / HH);
        sh_mu = mu;
        sh_rs = rsqrtf(tq * (1.f / HH) - mu * mu + 1e-5f);
    }
    __syncthreads();
    const float mu = sh_mu, rs = sh_rs;
    float a = fmaxf(0.f, (v.x - mu) * rs * g[tid * 2]     + beta[tid * 2]);
    float b = fmaxf(0.f, (v.y - mu) * rs * g[tid * 2 + 1] + beta[tid * 2 + 1]);
    __nv_bfloat162 p = __floats2bfloat162_rn(a, b);
    *(__nv_bfloat162*)(outb + (size_t)row * HH + tid * 2) = p;
}

// ---------------------------------------------------------------------------
// LayerNorm + ReLU + linear(384->1) + exp, fused.
// ---------------------------------------------------------------------------
__global__ __launch_bounds__(192)
void ln_linear_exp(const float* __restrict__ in, const float* __restrict__ g,
                   const float* __restrict__ beta, const float* __restrict__ wl,
                   const float* __restrict__ bl, float* __restrict__ pred)
{
    const int row = blockIdx.x, tid = threadIdx.x;
    const float2 v = *(const float2*)(in + (size_t)row * HH + tid * 2);
    float s = v.x + v.y, sq = v.x * v.x + v.y * v.y;
#pragma unroll
    for (int off = 16; off > 0; off >>= 1) {
        s  += __shfl_down_sync(0xffffffffu, s,  off);
        sq += __shfl_down_sync(0xffffffffu, sq, off);
    }
    __shared__ float rs_[6], rq_[6];
    const int wd = tid >> 5, ln = tid & 31;
    if (ln == 0) { rs_[wd] = s; rq_[wd] = sq; }
    __syncthreads();
    __shared__ float sh_mu, sh_rs;
    if (tid == 0) {
        float ts = 0.f, tq = 0.f;
#pragma unroll
        for (int i = 0; i < 6; i++) { ts += rs_[i]; tq += rq_[i]; }
        float mu = ts * (1.f / HH);
        sh_mu = mu;
        sh_rs = rsqrtf(tq * (1.f / HH) - mu * mu + 1e-5f);
    }
    __syncthreads();
    const float mu = sh_mu, rs = sh_rs;
    float a = fmaxf(0.f, (v.x - mu) * rs * g[tid * 2]     + beta[tid * 2]);
    float b = fmaxf(0.f, (v.y - mu) * rs * g[tid * 2 + 1] + beta[tid * 2 + 1]);
    float d = a * wl[tid * 2] + b * wl[tid * 2 + 1];
#pragma unroll
    for (int off = 16; off > 0; off >>= 1)
        d += __shfl_down_sync(0xffffffffu, d, off);
    __shared__ float rd_[6];
    if (ln == 0) rd_[wd] = d;
    __syncthreads();
    if (tid == 0) {
        float td = 0.f;
#pragma unroll
        for (int i = 0; i < 6; i++) td += rd_[i];
        pred[row] = expf(td + bl[0]);
    }
}

// ---------------------------------------------------------------------------
__global__ __launch_bounds__(256)
void f32_to_bf16(const float* __restrict__ x, __nv_bfloat16* __restrict__ y)
{
    const size_t i = ((size_t)blockIdx.x * 256 + threadIdx.x) * 4;
    float4 v = *(const float4*)(x + i);
    __nv_bfloat162 p0 = __floats2bfloat162_rn(v.x, v.y);
    __nv_bfloat162 p1 = __floats2bfloat162_rn(v.z, v.w);
    uint2 o;
    o.x = *(uint32_t*)&p0; o.y = *(uint32_t*)&p1;
    *(uint2*)(y + i) = o;
}

// Wt[n][kc] = W[kc][n], fp32 -> bf16
__global__ __launch_bounds__(256)
void wtrans(const float* __restrict__ w, __nv_bfloat16* __restrict__ wt)
{
    const int id = blockIdx.x * 256 + threadIdx.x;   // HH*KDIM = 442368 exact
    const int n  = id / KDIM;
    const int kc = id - n * KDIM;
    wt[id] = __float2bfloat16(w[(size_t)kc * HH + n]);
}

// ---------------------------------------------------------------------------
__global__ __launch_bounds__(1024)
void cumsum_kernel(const int* __restrict__ dur, int* __restrict__ cum)
{
    __shared__ int buf[SS];
    const int b = blockIdx.x, tid = threadIdx.x;
    buf[tid] = dur[b * SS + tid];
    __syncthreads();
#pragma unroll
    for (int off = 1; off < SS; off <<= 1) {
        int t = buf[tid];
        int u = (tid >= off) ? buf[tid - off] : 0;
        __syncthreads();
        buf[tid] = t + u;
        __syncthreads();
    }
    cum[b * SS + tid] = buf[tid];
}

__global__ __launch_bounds__(256)
void gather_kernel(const float* __restrict__ x, const int* __restrict__ cum,
                   float* __restrict__ out)
{
    const int gw   = (blockIdx.x * 256 + threadIdx.x) >> 5;
    const int lane = threadIdx.x & 31;
    const int b = gw / MAX_OUT_T;
    const int t = gw - b * MAX_OUT_T;

    const int* c = cum + b * SS;
    const bool valid = t < c[SS - 1];
    int lo = 0, hi = SS;
    while (lo < hi) {
        int mid = (lo + hi) >> 1;
        if (c[mid] <= t) lo = mid + 1; else hi = mid;
    }
    const int src = min(lo, SS - 1);

    const float4* xin = (const float4*)(x + ((size_t)b * SS + src) * CC);
    float4* o = (float4*)(out + (size_t)gw * CC);
    const float4 z = make_float4(0.f, 0.f, 0.f, 0.f);
#pragma unroll
    for (int i = 0; i < 3; i++)
        o[lane + i * 32] = valid ? xin[lane + i * 32] : z;
}

// ---------------------------------------------------------------------------
extern "C" void kernel_launch(void* const* d_in, const int* in_sizes, int n_in,
                              void* d_out, int out_size)
{
    const float* x     = (const float*)d_in[0];
    const int*   dur   = (const int*)  d_in[1];
    const float* w1    = (const float*)d_in[2];
    const float* b1    = (const float*)d_in[3];
    const float* g1    = (const float*)d_in[4];
    const float* beta1 = (const float*)d_in[5];
    const float* w2    = (const float*)d_in[6];
    const float* b2    = (const float*)d_in[7];
    const float* g2    = (const float*)d_in[8];
    const float* beta2 = (const float*)d_in[9];
    const float* wl    = (const float*)d_in[10];
    const float* bl    = (const float*)d_in[11];
    float* out = (float*)d_out;

    __nv_bfloat16 *xb, *h1b, *wt1, *wt2;
    float *tmp1, *tmp2; int* cum;
    cudaGetSymbolAddress((void**)&xb,   g_xb);
    cudaGetSymbolAddress((void**)&h1b,  g_h1b);
    cudaGetSymbolAddress((void**)&wt1,  g_wt1);
    cudaGetSymbolAddress((void**)&wt2,  g_wt2);
    cudaGetSymbolAddress((void**)&tmp1, g_tmp1);
    cudaGetSymbolAddress((void**)&tmp2, g_tmp2);
    cudaGetSymbolAddress((void**)&cum,  g_cum);

    cudaFuncSetAttribute(conv_gemm_mma, cudaFuncAttributeMaxDynamicSharedMemorySize, GEMM_SMEM);

    // input conversions
    f32_to_bf16<<<(M_TOTAL * CC) / 1024, 256>>>(x, xb);
    wtrans<<<(HH * KDIM) / 256, 256>>>(w1, wt1);
    wtrans<<<(HH * KDIM) / 256, 256>>>(w2, wt2);

    dim3 gemm_grid(HH / 128, M_TOTAL / 128);   // (3, 256)

    // duration predictor
    conv_gemm_mma<<<gemm_grid, 256, GEMM_SMEM>>>(xb, wt1, b1, tmp1);
    ln_relu_bf16<<<M_TOTAL, 192>>>(tmp1, g1, beta1, h1b);
    conv_gemm_mma<<<gemm_grid, 256, GEMM_SMEM>>>(h1b, wt2, b2, tmp2);
    ln_linear_exp<<<M_TOTAL, 192>>>(tmp2, g2, beta2, wl, bl, out + PRED_OFFSET);

    // length regulation
    cumsum_kernel<<<BB, SS>>>(dur, cum);
    gather_kernel<<<(BB * MAX_OUT_T) / 8, 256>>>(x, cum, out);
}

// round 4
// speedup vs baseline: 10.3546x; 1.1352x over previous
#include <cuda_runtime.h>
#include <cuda_bf16.h>
#include <math.h>
#include <stdint.h>

#define BB 32
#define SS 1024
#define CC 384
#define HH 384
#define MAX_OUT_T 3072
#define M_TOTAL (BB*SS)          // 32768
#define KDIM (3*CC)              // 1152
#define PRED_OFFSET ((size_t)BB*MAX_OUT_T*CC)

// ---------------- scratch (static device globals: allocation-free) ----------
__device__ __nv_bfloat16 g_xb [(size_t)M_TOTAL*CC];
__device__ __nv_bfloat16 g_h1b[(size_t)M_TOTAL*HH];
__device__ __nv_bfloat16 g_wt1[(size_t)HH*KDIM];
__device__ __nv_bfloat16 g_wt2[(size_t)HH*KDIM];
__device__ float g_tmp1[(size_t)M_TOTAL*HH];
__device__ float g_tmp2[(size_t)M_TOTAL*HH];
__device__ int   g_cum[BB*SS];

// ---------------- PTX helpers (baseline PTX only) ----------------------------
__device__ __forceinline__ uint32_t smem_u32(const void* p) {
    uint32_t a;
    asm("{ .reg .u64 t; cvta.to.shared.u64 t, %1; cvt.u32.u64 %0, t; }" : "=r"(a) : "l"(p));
    return a;
}
__device__ __forceinline__ void cp_async16(uint32_t saddr, const void* gptr, uint32_t sz) {
    asm volatile("cp.async.ca.shared.global [%0], [%1], 16, %2;"
                 :: "r"(saddr), "l"(gptr), "r"(sz) : "memory");
}
__device__ __forceinline__ void cp_commit() {
    asm volatile("cp.async.commit_group;" ::: "memory");
}
template <int N>
__device__ __forceinline__ void cp_wait() {
    asm volatile("cp.async.wait_group %0;" :: "n"(N) : "memory");
}
__device__ __forceinline__ void ldmatrix_x4(uint32_t& r0, uint32_t& r1, uint32_t& r2,
                                            uint32_t& r3, uint32_t addr) {
    asm volatile("ldmatrix.sync.aligned.m8n8.x4.shared.b16 {%0,%1,%2,%3}, [%4];"
                 : "=r"(r0), "=r"(r1), "=r"(r2), "=r"(r3) : "r"(addr));
}
__device__ __forceinline__ void mma_16816(float& d0, float& d1, float& d2, float& d3,
                                          uint32_t a0, uint32_t a1, uint32_t a2, uint32_t a3,
                                          uint32_t b0, uint32_t b1) {
    asm volatile("mma.sync.aligned.m16n8k16.row.col.f32.bf16.bf16.f32 "
                 "{%0,%1,%2,%3}, {%4,%5,%6,%7}, {%8,%9}, {%0,%1,%2,%3};"
                 : "+f"(d0), "+f"(d1), "+f"(d2), "+f"(d3)
                 : "r"(a0), "r"(a1), "r"(a2), "r"(a3), "r"(b0), "r"(b1));
}

// ---------------------------------------------------------------------------
// Conv-as-GEMM on tensor cores (mma.sync bf16), 3-stage cp.async pipeline.
//   out[m,n] = sum_kc A_im2col[m,kc] * Wt[n,kc] + bias[n]
// CTA tile 128x128; 8 warps as 2(m) x 4(n); warp tile 64x32.
// K = 1152 in 18 chunks of 64 bf16. __launch_bounds__(256,2) -> 2 CTA/SM.
// ---------------------------------------------------------------------------
#define NSTEPS 18
#define TILE_B 16384                       // 128 rows x 128 bytes
#define GEMM_SMEM (6*TILE_B)               // 3 stages x (A,B)

__global__ __launch_bounds__(256, 2)
void conv_gemm_mma(const __nv_bfloat16* __restrict__ A,
                   const __nv_bfloat16* __restrict__ Wt,
                   const float* __restrict__ bias,
                   float* __restrict__ out)
{
    extern __shared__ __align__(1024) char smem[];
    const uint32_t sbase = smem_u32(smem);
    const int tid  = threadIdx.x;
    const int wid  = tid >> 5;
    const int lane = tid & 31;
    const int warp_m = wid & 1;            // 0..1 -> 64-row halves
    const int warp_n = wid >> 1;           // 0..3 -> 32-col quarters
    const int n0 = blockIdx.x * 128;
    const int m0 = blockIdx.y * 128;

    // stage s: A at s*2*TILE_B, B at s*2*TILE_B + TILE_B
    // per-thread load geometry (4 segments of 16B per tile per thread)
    const int lrow = tid >> 3;              // 0..31 (+32*i)
    const int lcx  = (tid & 7) * 16;        // byte offset within 128B row

    auto load_tiles = [&](int step, int stage) {
        const uint32_t abase = sbase + (uint32_t)stage * 2 * TILE_B;
        const uint32_t bbase = abase + TILE_B;
        const int k  = step / 6;
        const int c0 = (step - k * 6) * 64;
#pragma unroll
        for (int i = 0; i < 4; i++) {
            const int row = lrow + 32 * i;
            uint32_t off = (uint32_t)(row * 128 + lcx);
            uint32_t sw  = off ^ ((off >> 3) & 0x70);
            // A (implicit im2col with zero halo via zfill)
            const int gm  = m0 + row;
            const int ss  = (gm & (SS - 1)) + k - 1;
            const bool valid = (ss >= 0) && (ss < SS);
            const char* gpa = (const char*)A + ((size_t)(gm + k - 1) * CC + c0) * 2 + lcx;
            if (!valid) gpa = (const char*)A;
            cp_async16(abase + sw, gpa, valid ? 16u : 0u);
            // B
            const char* gpb = (const char*)Wt + ((size_t)(n0 + row) * KDIM + step * 64) * 2 + lcx;
            cp_async16(bbase + sw, gpb, 16u);
        }
    };

    float acc[4][4][4];
#pragma unroll
    for (int i = 0; i < 4; i++)
#pragma unroll
        for (int j = 0; j < 4; j++)
#pragma unroll
            for (int q = 0; q < 4; q++) acc[i][j][q] = 0.f;

    // ldmatrix lane addressing
    const int fr_row = ((lane >> 3) & 1) * 8 + (lane & 7);  // row within 16-row frag
    const int fr_kb  = (lane >> 4) * 16;                    // 0 or 16 bytes

    // prologue: stages 0,1 hold steps 0,1
    load_tiles(0, 0); cp_commit();
    load_tiles(1, 1); cp_commit();

    int stage = 0;
    for (int step = 0; step < NSTEPS; ++step) {
        cp_wait<1>();
        __syncthreads();

        // prefetch step+2 into stage (stage+2)%3 == previous stage (safe: the
        // syncthreads above guarantees every warp finished computing it)
        {
            const int pf = stage + 2 - ((stage + 2 >= 3) ? 3 : 0);
            if (step + 2 < NSTEPS) load_tiles(step + 2, pf);
            cp_commit();                                // always commit (keeps group count uniform)
        }

        const uint32_t sa = sbase + (uint32_t)stage * 2 * TILE_B;
        const uint32_t sb = sa + TILE_B;

#pragma unroll
        for (int ks = 0; ks < 4; ks++) {                 // 4 x k16 within chunk
            uint32_t a[4][4];
#pragma unroll
            for (int mt = 0; mt < 4; mt++) {
                const int row = warp_m * 64 + mt * 16 + fr_row;
                uint32_t off = (uint32_t)(row * 128 + ks * 32 + fr_kb);
                uint32_t sw  = off ^ ((off >> 3) & 0x70);
                ldmatrix_x4(a[mt][0], a[mt][1], a[mt][2], a[mt][3], sa + sw);
            }
            uint32_t b[2][4];
#pragma unroll
            for (int nt = 0; nt < 2; nt++) {
                const int row = warp_n * 32 + nt * 16 + fr_row;
                uint32_t off = (uint32_t)(row * 128 + ks * 32 + fr_kb);
                uint32_t sw  = off ^ ((off >> 3) & 0x70);
                ldmatrix_x4(b[nt][0], b[nt][1], b[nt][2], b[nt][3], sb + sw);
            }
#pragma unroll
            for (int mt = 0; mt < 4; mt++)
#pragma unroll
                for (int nt = 0; nt < 2; nt++)
#pragma unroll
                    for (int h = 0; h < 2; h++) {
                        const int j = nt * 2 + h;
                        mma_16816(acc[mt][j][0], acc[mt][j][1], acc[mt][j][2], acc[mt][j][3],
                                  a[mt][0], a[mt][1], a[mt][2], a[mt][3],
                                  b[nt][h], b[nt][2 + h]);
                    }
        }
        stage = (stage == 2) ? 0 : stage + 1;
    }

    // ---- epilogue: bias add, float2 stores ---------------------------------
    const int g = lane >> 2;
    const int t = lane & 3;
#pragma unroll
    for (int mt = 0; mt < 4; mt++) {
        const int row0 = m0 + warp_m * 64 + mt * 16 + g;
#pragma unroll
        for (int j = 0; j < 4; j++) {
            const int col = n0 + warp_n * 32 + j * 8 + t * 2;
            const float2 bv = *(const float2*)(bias + col);
            float2 o0 = make_float2(acc[mt][j][0] + bv.x, acc[mt][j][1] + bv.y);
            float2 o1 = make_float2(acc[mt][j][2] + bv.x, acc[mt][j][3] + bv.y);
            *(float2*)(out + (size_t)row0 * HH + col)       = o0;
            *(float2*)(out + (size_t)(row0 + 8) * HH + col) = o1;
        }
    }
}

// ---------------------------------------------------------------------------
// LayerNorm + ReLU -> bf16 output (for conv2 input). 192 thr, 2 elems/thread.
// ---------------------------------------------------------------------------
__global__ __launch_bounds__(192)
void ln_relu_bf16(const float* __restrict__ in, const float* __restrict__ g,
                  const float* __restrict__ beta, __nv_bfloat16* __restrict__ outb)
{
    const int row = blockIdx.x, tid = threadIdx.x;
    const float2 v = *(const float2*)(in + (size_t)row * HH + tid * 2);
    float s = v.x + v.y, sq = v.x * v.x + v.y * v.y;
#pragma unroll
    for (int off = 16; off > 0; off >>= 1) {
        s  += __shfl_down_sync(0xffffffffu, s,  off);
        sq += __shfl_down_sync(0xffffffffu, sq, off);
    }
    __shared__ float rs_[6], rq_[6];
    const int wd = tid >> 5, ln = tid & 31;
    if (ln == 0) { rs_[wd] = s; rq_[wd] = sq; }
    __syncthreads();
    __shared__ float sh_mu, sh_rs;
    if (tid == 0) {
        float ts = 0.f, tq = 0.f;
#pragma unroll
        for (int i = 0; i < 6; i++) { ts += rs_[i]; tq += rq_[i]; }
        float mu = ts * (1.f / HH);
        sh_mu = mu;
        sh_rs = rsqrtf(tq * (1.f / HH) - mu * mu + 1e-5f);
    }
    __syncthreads();
    const float mu = sh_mu, rs = sh_rs;
    float a = fmaxf(0.f, (v.x - mu) * rs * g[tid * 2]     + beta[tid * 2]);
    float b = fmaxf(0.f, (v.y - mu) * rs * g[tid * 2 + 1] + beta[tid * 2 + 1]);
    __nv_bfloat162 p = __floats2bfloat162_rn(a, b);
    *(__nv_bfloat162*)(outb + (size_t)row * HH + tid * 2) = p;
}

// ---------------------------------------------------------------------------
// LayerNorm + ReLU + linear(384->1) + exp, fused.
// ---------------------------------------------------------------------------
__global__ __launch_bounds__(192)
void ln_linear_exp(const float* __restrict__ in, const float* __restrict__ g,
                   const float* __restrict__ beta, const float* __restrict__ wl,
                   const float* __restrict__ bl, float* __restrict__ pred)
{
    const int row = blockIdx.x, tid = threadIdx.x;
    const float2 v = *(const float2*)(in + (size_t)row * HH + tid * 2);
    float s = v.x + v.y, sq = v.x * v.x + v.y * v.y;
#pragma unroll
    for (int off = 16; off > 0; off >>= 1) {
        s  += __shfl_down_sync(0xffffffffu, s,  off);
        sq += __shfl_down_sync(0xffffffffu, sq, off);
    }
    __shared__ float rs_[6], rq_[6];
    const int wd = tid >> 5, ln = tid & 31;
    if (ln == 0) { rs_[wd] = s; rq_[wd] = sq; }
    __syncthreads();
    __shared__ float sh_mu, sh_rs;
    if (tid == 0) {
        float ts = 0.f, tq = 0.f;
#pragma unroll
        for (int i = 0; i < 6; i++) { ts += rs_[i]; tq += rq_[i]; }
        float mu = ts * (1.f / HH);
        sh_mu = mu;
        sh_rs = rsqrtf(tq * (1.f / HH) - mu * mu + 1e-5f);
    }
    __syncthreads();
    const float mu = sh_mu, rs = sh_rs;
    float a = fmaxf(0.f, (v.x - mu) * rs * g[tid * 2]     + beta[tid * 2]);
    float b = fmaxf(0.f, (v.y - mu) * rs * g[tid * 2 + 1] + beta[tid * 2 + 1]);
    float d = a * wl[tid * 2] + b * wl[tid * 2 + 1];
#pragma unroll
    for (int off = 16; off > 0; off >>= 1)
        d += __shfl_down_sync(0xffffffffu, d, off);
    __shared__ float rd_[6];
    if (ln == 0) rd_[wd] = d;
    __syncthreads();
    if (tid == 0) {
        float td = 0.f;
#pragma unroll
        for (int i = 0; i < 6; i++) td += rd_[i];
        pred[row] = expf(td + bl[0]);
    }
}

// ---------------------------------------------------------------------------
__global__ __launch_bounds__(256)
void f32_to_bf16(const float* __restrict__ x, __nv_bfloat16* __restrict__ y)
{
    const size_t i = ((size_t)blockIdx.x * 256 + threadIdx.x) * 4;
    float4 v = *(const float4*)(x + i);
    __nv_bfloat162 p0 = __floats2bfloat162_rn(v.x, v.y);
    __nv_bfloat162 p1 = __floats2bfloat162_rn(v.z, v.w);
    uint2 o;
    o.x = *(uint32_t*)&p0; o.y = *(uint32_t*)&p1;
    *(uint2*)(y + i) = o;
}

// Wt[n][kc] = W[kc][n], fp32 -> bf16
__global__ __launch_bounds__(256)
void wtrans(const float* __restrict__ w, __nv_bfloat16* __restrict__ wt)
{
    const int id = blockIdx.x * 256 + threadIdx.x;   // HH*KDIM = 442368 exact
    const int n  = id / KDIM;
    const int kc = id - n * KDIM;
    wt[id] = __float2bfloat16(w[(size_t)kc * HH + n]);
}

// ---------------------------------------------------------------------------
__global__ __launch_bounds__(1024)
void cumsum_kernel(const int* __restrict__ dur, int* __restrict__ cum)
{
    __shared__ int buf[SS];
    const int b = blockIdx.x, tid = threadIdx.x;
    buf[tid] = dur[b * SS + tid];
    __syncthreads();
#pragma unroll
    for (int off = 1; off < SS; off <<= 1) {
        int t = buf[tid];
        int u = (tid >= off) ? buf[tid - off] : 0;
        __syncthreads();
        buf[tid] = t + u;
        __syncthreads();
    }
    cum[b * SS + tid] = buf[tid];
}

__global__ __launch_bounds__(256)
void gather_kernel(const float* __restrict__ x, const int* __restrict__ cum,
                   float* __restrict__ out)
{
    const int gw   = (blockIdx.x * 256 + threadIdx.x) >> 5;
    const int lane = threadIdx.x & 31;
    const int b = gw / MAX_OUT_T;
    const int t = gw - b * MAX_OUT_T;

    const int* c = cum + b * SS;
    const bool valid = t < c[SS - 1];
    int lo = 0, hi = SS;
    while (lo < hi) {
        int mid = (lo + hi) >> 1;
        if (c[mid] <= t) lo = mid + 1; else hi = mid;
    }
    const int src = min(lo, SS - 1);

    const float4* xin = (const float4*)(x + ((size_t)b * SS + src) * CC);
    float4* o = (float4*)(out + (size_t)gw * CC);
    const float4 z = make_float4(0.f, 0.f, 0.f, 0.f);
#pragma unroll
    for (int i = 0; i < 3; i++)
        o[lane + i * 32] = valid ? xin[lane + i * 32] : z;
}

// ---------------------------------------------------------------------------
extern "C" void kernel_launch(void* const* d_in, const int* in_sizes, int n_in,
                              void* d_out, int out_size)
{
    const float* x     = (const float*)d_in[0];
    const int*   dur   = (const int*)  d_in[1];
    const float* w1    = (const float*)d_in[2];
    const float* b1    = (const float*)d_in[3];
    const float* g1    = (const float*)d_in[4];
    const float* beta1 = (const float*)d_in[5];
    const float* w2    = (const float*)d_in[6];
    const float* b2    = (const float*)d_in[7];
    const float* g2    = (const float*)d_in[8];
    const float* beta2 = (const float*)d_in[9];
    const float* wl    = (const float*)d_in[10];
    const float* bl    = (const float*)d_in[11];
    float* out = (float*)d_out;

    __nv_bfloat16 *xb, *h1b, *wt1, *wt2;
    float *tmp1, *tmp2; int* cum;
    cudaGetSymbolAddress((void**)&xb,   g_xb);
    cudaGetSymbolAddress((void**)&h1b,  g_h1b);
    cudaGetSymbolAddress((void**)&wt1,  g_wt1);
    cudaGetSymbolAddress((void**)&wt2,  g_wt2);
    cudaGetSymbolAddress((void**)&tmp1, g_tmp1);
    cudaGetSymbolAddress((void**)&tmp2, g_tmp2);
    cudaGetSymbolAddress((void**)&cum,  g_cum);

    cudaFuncSetAttribute(conv_gemm_mma, cudaFuncAttributeMaxDynamicSharedMemorySize, GEMM_SMEM);

    // input conversions
    f32_to_bf16<<<(M_TOTAL * CC) / 1024, 256>>>(x, xb);
    wtrans<<<(HH * KDIM) / 256, 256>>>(w1, wt1);
    wtrans<<<(HH * KDIM) / 256, 256>>>(w2, wt2);

    dim3 gemm_grid(HH / 128, M_TOTAL / 128);   // (3, 256)

    // duration predictor
    conv_gemm_mma<<<gemm_grid, 256, GEMM_SMEM>>>(xb, wt1, b1, tmp1);
    ln_relu_bf16<<<M_TOTAL, 192>>>(tmp1, g1, beta1, h1b);
    conv_gemm_mma<<<gemm_grid, 256, GEMM_SMEM>>>(h1b, wt2, b2, tmp2);
    ln_linear_exp<<<M_TOTAL, 192>>>(tmp2, g2, beta2, wl, bl, out + PRED_OFFSET);

    // length regulation
    cumsum_kernel<<<BB, SS>>>(dur, cum);
    gather_kernel<<<(BB * MAX_OUT_T) / 8, 256>>>(x, cum, out);
}

// round 5
// speedup vs baseline: 10.7344x; 1.0367x over previous
#include <cuda_runtime.h>
#include <cuda_bf16.h>
#include <math.h>
#include <stdint.h>

#define BB 32
#define SS 1024
#define CC 384
#define HH 384
#define MAX_OUT_T 3072
#define M_TOTAL (BB*SS)          // 32768
#define KDIM (3*CC)              // 1152
#define PRED_OFFSET ((size_t)BB*MAX_OUT_T*CC)

// ---------------- scratch (static device globals: allocation-free) ----------
__device__ __nv_bfloat16 g_xb [(size_t)M_TOTAL*CC];
__device__ __nv_bfloat16 g_h1b[(size_t)M_TOTAL*HH];
__device__ __nv_bfloat16 g_wt1[(size_t)HH*KDIM];
__device__ __nv_bfloat16 g_wt2[(size_t)HH*KDIM];
__device__ float g_tmp1[(size_t)M_TOTAL*HH];
__device__ float g_tmp2[(size_t)M_TOTAL*HH];
__device__ int   g_cum[BB*SS];

// ---------------- PTX helpers (baseline PTX only) ----------------------------
__device__ __forceinline__ uint32_t smem_u32(const void* p) {
    uint32_t a;
    asm("{ .reg .u64 t; cvta.to.shared.u64 t, %1; cvt.u32.u64 %0, t; }" : "=r"(a) : "l"(p));
    return a;
}
__device__ __forceinline__ void cp_async16(uint32_t saddr, const void* gptr, uint32_t sz) {
    asm volatile("cp.async.cg.shared.global [%0], [%1], 16, %2;"
                 :: "r"(saddr), "l"(gptr), "r"(sz) : "memory");
}
__device__ __forceinline__ void cp_commit() {
    asm volatile("cp.async.commit_group;" ::: "memory");
}
template <int N>
__device__ __forceinline__ void cp_wait() {
    asm volatile("cp.async.wait_group %0;" :: "n"(N) : "memory");
}
__device__ __forceinline__ void ldmatrix_x4(uint32_t& r0, uint32_t& r1, uint32_t& r2,
                                            uint32_t& r3, uint32_t addr) {
    asm volatile("ldmatrix.sync.aligned.m8n8.x4.shared.b16 {%0,%1,%2,%3}, [%4];"
                 : "=r"(r0), "=r"(r1), "=r"(r2), "=r"(r3) : "r"(addr));
}
__device__ __forceinline__ void mma_16816(float& d0, float& d1, float& d2, float& d3,
                                          uint32_t a0, uint32_t a1, uint32_t a2, uint32_t a3,
                                          uint32_t b0, uint32_t b1) {
    asm volatile("mma.sync.aligned.m16n8k16.row.col.f32.bf16.bf16.f32 "
                 "{%0,%1,%2,%3}, {%4,%5,%6,%7}, {%8,%9}, {%0,%1,%2,%3};"
                 : "+f"(d0), "+f"(d1), "+f"(d2), "+f"(d3)
                 : "r"(a0), "r"(a1), "r"(a2), "r"(a3), "r"(b0), "r"(b1));
}

// ---------------------------------------------------------------------------
// Conv-as-GEMM on tensor cores (mma.sync bf16), 3-stage cp.async pipeline.
// CTA tile 128x128; 8 warps 2(m) x 4(n); warp tile 64x32.
// B fragments hoisted per step; A fragments loaded per-ks (overlaps with MMA).
// ---------------------------------------------------------------------------
#define NSTEPS 18
#define TILE_B 16384                       // 128 rows x 128 bytes
#define GEMM_SMEM (6*TILE_B)               // 3 stages x (A,B)

__global__ __launch_bounds__(256, 2)
void conv_gemm_mma(const __nv_bfloat16* __restrict__ A,
                   const __nv_bfloat16* __restrict__ Wt,
                   const float* __restrict__ bias,
                   float* __restrict__ out)
{
    extern __shared__ __align__(1024) char smem[];
    const uint32_t sbase = smem_u32(smem);
    const int tid  = threadIdx.x;
    const int wid  = tid >> 5;
    const int lane = tid & 31;
    const int warp_m = wid & 1;            // 0..1 -> 64-row halves
    const int warp_n = wid >> 1;           // 0..3 -> 32-col quarters
    const int n0 = blockIdx.x * 128;
    const int m0 = blockIdx.y * 128;

    // per-thread load geometry (4 segments of 16B per tile per thread)
    const int lrow = tid >> 3;              // 0..31 (+32*i)
    const int lcx  = (tid & 7) * 16;        // byte offset within 128B row

    auto load_tiles = [&](int step, int stage) {
        const uint32_t abase = sbase + (uint32_t)stage * 2 * TILE_B;
        const uint32_t bbase = abase + TILE_B;
        const int k  = step / 6;
        const int c0 = (step - k * 6) * 64;
#pragma unroll
        for (int i = 0; i < 4; i++) {
            const int row = lrow + 32 * i;
            uint32_t off = (uint32_t)(row * 128 + lcx);
            uint32_t sw  = off ^ ((off >> 3) & 0x70);
            // A (implicit im2col with zero halo via zfill)
            const int gm  = m0 + row;
            const int ss  = (gm & (SS - 1)) + k - 1;
            const bool valid = (ss >= 0) && (ss < SS);
            const char* gpa = (const char*)A + ((size_t)(gm + k - 1) * CC + c0) * 2 + lcx;
            if (!valid) gpa = (const char*)A;
            cp_async16(abase + sw, gpa, valid ? 16u : 0u);
            // B
            const char* gpb = (const char*)Wt + ((size_t)(n0 + row) * KDIM + step * 64) * 2 + lcx;
            cp_async16(bbase + sw, gpb, 16u);
        }
    };

    float acc[4][4][4];
#pragma unroll
    for (int i = 0; i < 4; i++)
#pragma unroll
        for (int j = 0; j < 4; j++)
#pragma unroll
            for (int q = 0; q < 4; q++) acc[i][j][q] = 0.f;

    // ldmatrix lane addressing: swizzle reduced to a per-lane XOR constant.
    // off = row*128 + col (col<128) -> sw = row*128 + (col ^ ((row&7)<<4))
    const int fr_row = ((lane >> 3) & 1) * 8 + (lane & 7);  // row within 16-row frag
    const int fr_kb  = (lane >> 4) * 16;                    // 0 or 16 bytes
    const uint32_t cxor = (uint32_t)((fr_row & 7) << 4);
    // per-warp row bases (bytes)
    const uint32_t a_row_base = (uint32_t)((warp_m * 64 + fr_row) * 128);
    const uint32_t b_row_base = (uint32_t)((warp_n * 32 + fr_row) * 128);

    // prologue: stages 0,1 hold steps 0,1
    load_tiles(0, 0); cp_commit();
    load_tiles(1, 1); cp_commit();

    int stage = 0;
    for (int step = 0; step < NSTEPS; ++step) {
        cp_wait<1>();
        __syncthreads();

        // prefetch step+2 into the stage we just vacated
        {
            const int pf = stage + 2 - ((stage + 2 >= 3) ? 3 : 0);
            if (step + 2 < NSTEPS) load_tiles(step + 2, pf);
            cp_commit();
        }

        const uint32_t sa = sbase + (uint32_t)stage * 2 * TILE_B;
        const uint32_t sb = sa + TILE_B;

        // ---- hoist ALL B fragments for this step (8 LDSM, 32 regs) ----
        uint32_t ball[4][2][4];
#pragma unroll
        for (int ks = 0; ks < 4; ks++) {
            const uint32_t col = ((uint32_t)(ks * 32 + fr_kb)) ^ cxor;
#pragma unroll
            for (int nt = 0; nt < 2; nt++) {
                const uint32_t addr = sb + b_row_base + (uint32_t)(nt * 2048) + col;
                ldmatrix_x4(ball[ks][nt][0], ball[ks][nt][1], ball[ks][nt][2], ball[ks][nt][3], addr);
            }
        }

#pragma unroll
        for (int ks = 0; ks < 4; ks++) {
            const uint32_t col = ((uint32_t)(ks * 32 + fr_kb)) ^ cxor;
            uint32_t a[4][4];
#pragma unroll
            for (int mt = 0; mt < 4; mt++) {
                const uint32_t addr = sa + a_row_base + (uint32_t)(mt * 2048) + col;
                ldmatrix_x4(a[mt][0], a[mt][1], a[mt][2], a[mt][3], addr);
            }
#pragma unroll
            for (int mt = 0; mt < 4; mt++)
#pragma unroll
                for (int nt = 0; nt < 2; nt++)
#pragma unroll
                    for (int h = 0; h < 2; h++) {
                        const int j = nt * 2 + h;
                        mma_16816(acc[mt][j][0], acc[mt][j][1], acc[mt][j][2], acc[mt][j][3],
                                  a[mt][0], a[mt][1], a[mt][2], a[mt][3],
                                  ball[ks][nt][h], ball[ks][nt][2 + h]);
                    }
        }
        stage = (stage == 2) ? 0 : stage + 1;
    }

    // ---- epilogue: bias add, float2 stores ---------------------------------
    const int g = lane >> 2;
    const int t = lane & 3;
#pragma unroll
    for (int mt = 0; mt < 4; mt++) {
        const int row0 = m0 + warp_m * 64 + mt * 16 + g;
#pragma unroll
        for (int j = 0; j < 4; j++) {
            const int col = n0 + warp_n * 32 + j * 8 + t * 2;
            const float2 bv = *(const float2*)(bias + col);
            float2 o0 = make_float2(acc[mt][j][0] + bv.x, acc[mt][j][1] + bv.y);
            float2 o1 = make_float2(acc[mt][j][2] + bv.x, acc[mt][j][3] + bv.y);
            *(float2*)(out + (size_t)row0 * HH + col)       = o0;
            *(float2*)(out + (size_t)(row0 + 8) * HH + col) = o1;
        }
    }
}

// ---------------------------------------------------------------------------
// LayerNorm + ReLU -> bf16 output (for conv2 input). 192 thr, 2 elems/thread.
// ---------------------------------------------------------------------------
__global__ __launch_bounds__(192)
void ln_relu_bf16(const float* __restrict__ in, const float* __restrict__ g,
                  const float* __restrict__ beta, __nv_bfloat16* __restrict__ outb)
{
    const int row = blockIdx.x, tid = threadIdx.x;
    const float2 v = *(const float2*)(in + (size_t)row * HH + tid * 2);
    float s = v.x + v.y, sq = v.x * v.x + v.y * v.y;
#pragma unroll
    for (int off = 16; off > 0; off >>= 1) {
        s  += __shfl_down_sync(0xffffffffu, s,  off);
        sq += __shfl_down_sync(0xffffffffu, sq, off);
    }
    __shared__ float rs_[6], rq_[6];
    const int wd = tid >> 5, ln = tid & 31;
    if (ln == 0) { rs_[wd] = s; rq_[wd] = sq; }
    __syncthreads();
    __shared__ float sh_mu, sh_rs;
    if (tid == 0) {
        float ts = 0.f, tq = 0.f;
#pragma unroll
        for (int i = 0; i < 6; i++) { ts += rs_[i]; tq += rq_[i]; }
        float mu = ts * (1.f / HH);
        sh_mu = mu;
        sh_rs = rsqrtf(tq * (1.f / HH) - mu * mu + 1e-5f);
    }
    __syncthreads();
    const float mu = sh_mu, rs = sh_rs;
    float a = fmaxf(0.f, (v.x - mu) * rs * g[tid * 2]     + beta[tid * 2]);
    float b = fmaxf(0.f, (v.y - mu) * rs * g[tid * 2 + 1] + beta[tid * 2 + 1]);
    __nv_bfloat162 p = __floats2bfloat162_rn(a, b);
    *(__nv_bfloat162*)(outb + (size_t)row * HH + tid * 2) = p;
}

// ---------------------------------------------------------------------------
// LayerNorm + ReLU + linear(384->1) + exp, fused.
// ---------------------------------------------------------------------------
__global__ __launch_bounds__(192)
void ln_linear_exp(const float* __restrict__ in, const float* __restrict__ g,
                   const float* __restrict__ beta, const float* __restrict__ wl,
                   const float* __restrict__ bl, float* __restrict__ pred)
{
    const int row = blockIdx.x, tid = threadIdx.x;
    const float2 v = *(const float2*)(in + (size_t)row * HH + tid * 2);
    float s = v.x + v.y, sq = v.x * v.x + v.y * v.y;
#pragma unroll
    for (int off = 16; off > 0; off >>= 1) {
        s  += __shfl_down_sync(0xffffffffu, s,  off);
        sq += __shfl_down_sync(0xffffffffu, sq, off);
    }
    __shared__ float rs_[6], rq_[6];
    const int wd = tid >> 5, ln = tid & 31;
    if (ln == 0) { rs_[wd] = s; rq_[wd] = sq; }
    __syncthreads();
    __shared__ float sh_mu, sh_rs;
    if (tid == 0) {
        float ts = 0.f, tq = 0.f;
#pragma unroll
        for (int i = 0; i < 6; i++) { ts += rs_[i]; tq += rq_[i]; }
        float mu = ts * (1.f / HH);
        sh_mu = mu;
        sh_rs = rsqrtf(tq * (1.f / HH) - mu * mu + 1e-5f);
    }
    __syncthreads();
    const float mu = sh_mu, rs = sh_rs;
    float a = fmaxf(0.f, (v.x - mu) * rs * g[tid * 2]     + beta[tid * 2]);
    float b = fmaxf(0.f, (v.y - mu) * rs * g[tid * 2 + 1] + beta[tid * 2 + 1]);
    float d = a * wl[tid * 2] + b * wl[tid * 2 + 1];
#pragma unroll
    for (int off = 16; off > 0; off >>= 1)
        d += __shfl_down_sync(0xffffffffu, d, off);
    __shared__ float rd_[6];
    if (ln == 0) rd_[wd] = d;
    __syncthreads();
    if (tid == 0) {
        float td = 0.f;
#pragma unroll
        for (int i = 0; i < 6; i++) td += rd_[i];
        pred[row] = expf(td + bl[0]);
    }
}

// ---------------------------------------------------------------------------
__global__ __launch_bounds__(256)
void f32_to_bf16(const float* __restrict__ x, __nv_bfloat16* __restrict__ y)
{
    const size_t i = ((size_t)blockIdx.x * 256 + threadIdx.x) * 4;
    float4 v = *(const float4*)(x + i);
    __nv_bfloat162 p0 = __floats2bfloat162_rn(v.x, v.y);
    __nv_bfloat162 p1 = __floats2bfloat162_rn(v.z, v.w);
    uint2 o;
    o.x = *(uint32_t*)&p0; o.y = *(uint32_t*)&p1;
    *(uint2*)(y + i) = o;
}

// Wt[n][kc] = W[kc][n], fp32 -> bf16. blockIdx.y selects weight set.
__global__ __launch_bounds__(256)
void wtrans2(const float* __restrict__ w1, __nv_bfloat16* __restrict__ wt1,
             const float* __restrict__ w2, __nv_bfloat16* __restrict__ wt2)
{
    const int id = blockIdx.x * 256 + threadIdx.x;   // HH*KDIM = 442368 exact
    const int n  = id / KDIM;
    const int kc = id - n * KDIM;
    if (blockIdx.y == 0) wt1[id] = __float2bfloat16(w1[(size_t)kc * HH + n]);
    else                 wt2[id] = __float2bfloat16(w2[(size_t)kc * HH + n]);
}

// ---------------------------------------------------------------------------
__global__ __launch_bounds__(1024)
void cumsum_kernel(const int* __restrict__ dur, int* __restrict__ cum)
{
    __shared__ int buf[SS];
    const int b = blockIdx.x, tid = threadIdx.x;
    buf[tid] = dur[b * SS + tid];
    __syncthreads();
#pragma unroll
    for (int off = 1; off < SS; off <<= 1) {
        int t = buf[tid];
        int u = (tid >= off) ? buf[tid - off] : 0;
        __syncthreads();
        buf[tid] = t + u;
        __syncthreads();
    }
    cum[b * SS + tid] = buf[tid];
}

__global__ __launch_bounds__(256)
void gather_kernel(const float* __restrict__ x, const int* __restrict__ cum,
                   float* __restrict__ out)
{
    const int gw   = (blockIdx.x * 256 + threadIdx.x) >> 5;
    const int lane = threadIdx.x & 31;
    const int b = gw / MAX_OUT_T;
    const int t = gw - b * MAX_OUT_T;

    const int* c = cum + b * SS;
    const bool valid = t < c[SS - 1];
    int lo = 0, hi = SS;
    while (lo < hi) {
        int mid = (lo + hi) >> 1;
        if (c[mid] <= t) lo = mid + 1; else hi = mid;
    }
    const int src = min(lo, SS - 1);

    const float4* xin = (const float4*)(x + ((size_t)b * SS + src) * CC);
    float4* o = (float4*)(out + (size_t)gw * CC);
    const float4 z = make_float4(0.f, 0.f, 0.f, 0.f);
#pragma unroll
    for (int i = 0; i < 3; i++)
        o[lane + i * 32] = valid ? xin[lane + i * 32] : z;
}

// ---------------------------------------------------------------------------
extern "C" void kernel_launch(void* const* d_in, const int* in_sizes, int n_in,
                              void* d_out, int out_size)
{
    const float* x     = (const float*)d_in[0];
    const int*   dur   = (const int*)  d_in[1];
    const float* w1    = (const float*)d_in[2];
    const float* b1    = (const float*)d_in[3];
    const float* g1    = (const float*)d_in[4];
    const float* beta1 = (const float*)d_in[5];
    const float* w2    = (const float*)d_in[6];
    const float* b2    = (const float*)d_in[7];
    const float* g2    = (const float*)d_in[8];
    const float* beta2 = (const float*)d_in[9];
    const float* wl    = (const float*)d_in[10];
    const float* bl    = (const float*)d_in[11];
    float* out = (float*)d_out;

    __nv_bfloat16 *xb, *h1b, *wt1, *wt2;
    float *tmp1, *tmp2; int* cum;
    cudaGetSymbolAddress((void**)&xb,   g_xb);
    cudaGetSymbolAddress((void**)&h1b,  g_h1b);
    cudaGetSymbolAddress((void**)&wt1,  g_wt1);
    cudaGetSymbolAddress((void**)&wt2,  g_wt2);
    cudaGetSymbolAddress((void**)&tmp1, g_tmp1);
    cudaGetSymbolAddress((void**)&tmp2, g_tmp2);
    cudaGetSymbolAddress((void**)&cum,  g_cum);

    cudaFuncSetAttribute(conv_gemm_mma, cudaFuncAttributeMaxDynamicSharedMemorySize, GEMM_SMEM);

    // input conversions
    f32_to_bf16<<<(M_TOTAL * CC) / 1024, 256>>>(x, xb);
    {
        dim3 wg((HH * KDIM) / 256, 2);
        wtrans2<<<wg, 256>>>(w1, wt1, w2, wt2);
    }

    dim3 gemm_grid(HH / 128, M_TOTAL / 128);   // (3, 256)

    // duration predictor
    conv_gemm_mma<<<gemm_grid, 256, GEMM_SMEM>>>(xb, wt1, b1, tmp1);
    ln_relu_bf16<<<M_TOTAL, 192>>>(tmp1, g1, beta1, h1b);
    conv_gemm_mma<<<gemm_grid, 256, GEMM_SMEM>>>(h1b, wt2, b2, tmp2);
    ln_linear_exp<<<M_TOTAL, 192>>>(tmp2, g2, beta2, wl, bl, out + PRED_OFFSET);

    // length regulation
    cumsum_kernel<<<BB, SS>>>(dur, cum);
    gather_kernel<<<(BB * MAX_OUT_T) / 8, 256>>>(x, cum, out);
}

// round 6
// speedup vs baseline: 12.1583x; 1.1327x over previous
#include <cuda_runtime.h>
#include <cuda_bf16.h>
#include <math.h>
#include <stdint.h>

#define BB 32
#define SS 1024
#define CC 384
#define HH 384
#define MAX_OUT_T 3072
#define M_TOTAL (BB*SS)          // 32768
#define KDIM (3*CC)              // 1152
#define PRED_OFFSET ((size_t)BB*MAX_OUT_T*CC)

// ---------------- scratch (static device globals: allocation-free) ----------
__device__ __nv_bfloat16 g_xb [(size_t)M_TOTAL*CC];
__device__ __nv_bfloat16 g_h1b[(size_t)M_TOTAL*HH];
__device__ __nv_bfloat16 g_wt1[(size_t)HH*KDIM];
__device__ __nv_bfloat16 g_wt2[(size_t)HH*KDIM];
__device__ float g_tmp1[(size_t)M_TOTAL*HH];
__device__ float g_tmp2[(size_t)M_TOTAL*HH];
__device__ int   g_cum[BB*SS];

// ---------------- PTX helpers (baseline PTX only) ----------------------------
__device__ __forceinline__ uint32_t smem_u32(const void* p) {
    uint32_t a;
    asm("{ .reg .u64 t; cvta.to.shared.u64 t, %1; cvt.u32.u64 %0, t; }" : "=r"(a) : "l"(p));
    return a;
}
__device__ __forceinline__ void cp_async16(uint32_t saddr, const void* gptr, uint32_t sz) {
    asm volatile("cp.async.cg.shared.global [%0], [%1], 16, %2;"
                 :: "r"(saddr), "l"(gptr), "r"(sz) : "memory");
}
__device__ __forceinline__ void cp_commit() {
    asm volatile("cp.async.commit_group;" ::: "memory");
}
template <int N>
__device__ __forceinline__ void cp_wait() {
    asm volatile("cp.async.wait_group %0;" :: "n"(N) : "memory");
}
__device__ __forceinline__ void ldmatrix_x4(uint32_t& r0, uint32_t& r1, uint32_t& r2,
                                            uint32_t& r3, uint32_t addr) {
    asm volatile("ldmatrix.sync.aligned.m8n8.x4.shared.b16 {%0,%1,%2,%3}, [%4];"
                 : "=r"(r0), "=r"(r1), "=r"(r2), "=r"(r3) : "r"(addr));
}
__device__ __forceinline__ void mma_16816(float& d0, float& d1, float& d2, float& d3,
                                          uint32_t a0, uint32_t a1, uint32_t a2, uint32_t a3,
                                          uint32_t b0, uint32_t b1) {
    asm volatile("mma.sync.aligned.m16n8k16.row.col.f32.bf16.bf16.f32 "
                 "{%0,%1,%2,%3}, {%4,%5,%6,%7}, {%8,%9}, {%0,%1,%2,%3};"
                 : "+f"(d0), "+f"(d1), "+f"(d2), "+f"(d3)
                 : "r"(a0), "r"(a1), "r"(a2), "r"(a3), "r"(b0), "r"(b1));
}

// ---------------------------------------------------------------------------
// Conv-as-GEMM on tensor cores (mma.sync bf16), 3-stage cp.async pipeline.
// CTA tile 128x128; 8 warps 2(m) x 4(n); warp tile 64x32.
// ---------------------------------------------------------------------------
#define NSTEPS 18
#define TILE_B 16384                       // 128 rows x 128 bytes
#define GEMM_SMEM (6*TILE_B)               // 3 stages x (A,B)

__global__ __launch_bounds__(256, 2)
void conv_gemm_mma(const __nv_bfloat16* __restrict__ A,
                   const __nv_bfloat16* __restrict__ Wt,
                   const float* __restrict__ bias,
                   float* __restrict__ out)
{
    extern __shared__ __align__(1024) char smem[];
    const uint32_t sbase = smem_u32(smem);
    const int tid  = threadIdx.x;
    const int wid  = tid >> 5;
    const int lane = tid & 31;
    const int warp_m = wid & 1;
    const int warp_n = wid >> 1;
    const int n0 = blockIdx.x * 128;
    const int m0 = blockIdx.y * 128;

    const int lrow = tid >> 3;              // 0..31 (+32*i)
    const int lcx  = (tid & 7) * 16;

    auto load_tiles = [&](int step, int stage) {
        const uint32_t abase = sbase + (uint32_t)stage * 2 * TILE_B;
        const uint32_t bbase = abase + TILE_B;
        const int k  = step / 6;
        const int c0 = (step - k * 6) * 64;
#pragma unroll
        for (int i = 0; i < 4; i++) {
            const int row = lrow + 32 * i;
            uint32_t off = (uint32_t)(row * 128 + lcx);
            uint32_t sw  = off ^ ((off >> 3) & 0x70);
            const int gm  = m0 + row;
            const int ss  = (gm & (SS - 1)) + k - 1;
            const bool valid = (ss >= 0) && (ss < SS);
            const char* gpa = (const char*)A + ((size_t)(gm + k - 1) * CC + c0) * 2 + lcx;
            if (!valid) gpa = (const char*)A;
            cp_async16(abase + sw, gpa, valid ? 16u : 0u);
            const char* gpb = (const char*)Wt + ((size_t)(n0 + row) * KDIM + step * 64) * 2 + lcx;
            cp_async16(bbase + sw, gpb, 16u);
        }
    };

    float acc[4][4][4];
#pragma unroll
    for (int i = 0; i < 4; i++)
#pragma unroll
        for (int j = 0; j < 4; j++)
#pragma unroll
            for (int q = 0; q < 4; q++) acc[i][j][q] = 0.f;

    const int fr_row = ((lane >> 3) & 1) * 8 + (lane & 7);
    const int fr_kb  = (lane >> 4) * 16;
    const uint32_t cxor = (uint32_t)((fr_row & 7) << 4);
    const uint32_t a_row_base = (uint32_t)((warp_m * 64 + fr_row) * 128);
    const uint32_t b_row_base = (uint32_t)((warp_n * 32 + fr_row) * 128);

    load_tiles(0, 0); cp_commit();
    load_tiles(1, 1); cp_commit();

    int stage = 0;
    for (int step = 0; step < NSTEPS; ++step) {
        cp_wait<1>();
        __syncthreads();

        {
            const int pf = stage + 2 - ((stage + 2 >= 3) ? 3 : 0);
            if (step + 2 < NSTEPS) load_tiles(step + 2, pf);
            cp_commit();
        }

        const uint32_t sa = sbase + (uint32_t)stage * 2 * TILE_B;
        const uint32_t sb = sa + TILE_B;

        uint32_t ball[4][2][4];
#pragma unroll
        for (int ks = 0; ks < 4; ks++) {
            const uint32_t col = ((uint32_t)(ks * 32 + fr_kb)) ^ cxor;
#pragma unroll
            for (int nt = 0; nt < 2; nt++) {
                const uint32_t addr = sb + b_row_base + (uint32_t)(nt * 2048) + col;
                ldmatrix_x4(ball[ks][nt][0], ball[ks][nt][1], ball[ks][nt][2], ball[ks][nt][3], addr);
            }
        }

#pragma unroll
        for (int ks = 0; ks < 4; ks++) {
            const uint32_t col = ((uint32_t)(ks * 32 + fr_kb)) ^ cxor;
            uint32_t a[4][4];
#pragma unroll
            for (int mt = 0; mt < 4; mt++) {
                const uint32_t addr = sa + a_row_base + (uint32_t)(mt * 2048) + col;
                ldmatrix_x4(a[mt][0], a[mt][1], a[mt][2], a[mt][3], addr);
            }
#pragma unroll
            for (int mt = 0; mt < 4; mt++)
#pragma unroll
                for (int nt = 0; nt < 2; nt++)
#pragma unroll
                    for (int h = 0; h < 2; h++) {
                        const int j = nt * 2 + h;
                        mma_16816(acc[mt][j][0], acc[mt][j][1], acc[mt][j][2], acc[mt][j][3],
                                  a[mt][0], a[mt][1], a[mt][2], a[mt][3],
                                  ball[ks][nt][h], ball[ks][nt][2 + h]);
                    }
        }
        stage = (stage == 2) ? 0 : stage + 1;
    }

    const int g = lane >> 2;
    const int t = lane & 3;
#pragma unroll
    for (int mt = 0; mt < 4; mt++) {
        const int row0 = m0 + warp_m * 64 + mt * 16 + g;
#pragma unroll
        for (int j = 0; j < 4; j++) {
            const int col = n0 + warp_n * 32 + j * 8 + t * 2;
            const float2 bv = *(const float2*)(bias + col);
            float2 o0 = make_float2(acc[mt][j][0] + bv.x, acc[mt][j][1] + bv.y);
            float2 o1 = make_float2(acc[mt][j][2] + bv.x, acc[mt][j][3] + bv.y);
            *(float2*)(out + (size_t)row0 * HH + col)       = o0;
            *(float2*)(out + (size_t)(row0 + 8) * HH + col) = o1;
        }
    }
}

// ---------------------------------------------------------------------------
// Warp-per-row LayerNorm + ReLU -> bf16. float4 loads, butterfly reductions,
// no smem, no block barriers. 8 rows per 256-thread block.
// ---------------------------------------------------------------------------
__global__ __launch_bounds__(256)
void ln_relu_bf16(const float* __restrict__ in, const float* __restrict__ g,
                  const float* __restrict__ beta, __nv_bfloat16* __restrict__ outb)
{
    const int row  = (blockIdx.x * 256 + threadIdx.x) >> 5;
    const int lane = threadIdx.x & 31;
    const float4* p = (const float4*)(in + (size_t)row * HH);

    float4 v[3];
    float s = 0.f, sq = 0.f;
#pragma unroll
    for (int i = 0; i < 3; i++) {
        v[i] = p[lane + 32 * i];
        s  += v[i].x + v[i].y + v[i].z + v[i].w;
        sq += v[i].x * v[i].x + v[i].y * v[i].y + v[i].z * v[i].z + v[i].w * v[i].w;
    }
#pragma unroll
    for (int off = 16; off > 0; off >>= 1) {
        s  += __shfl_xor_sync(0xffffffffu, s,  off);
        sq += __shfl_xor_sync(0xffffffffu, sq, off);
    }
    const float mu = s * (1.f / HH);
    const float rs = rsqrtf(sq * (1.f / HH) - mu * mu + 1e-5f);

    __nv_bfloat16* op = outb + (size_t)row * HH;
#pragma unroll
    for (int i = 0; i < 3; i++) {
        const int c = (lane + 32 * i) * 4;
        const float4 gv = *(const float4*)(g + c);
        const float4 bv = *(const float4*)(beta + c);
        float o0 = fmaxf(0.f, (v[i].x - mu) * rs * gv.x + bv.x);
        float o1 = fmaxf(0.f, (v[i].y - mu) * rs * gv.y + bv.y);
        float o2 = fmaxf(0.f, (v[i].z - mu) * rs * gv.z + bv.z);
        float o3 = fmaxf(0.f, (v[i].w - mu) * rs * gv.w + bv.w);
        __nv_bfloat162 p0 = __floats2bfloat162_rn(o0, o1);
        __nv_bfloat162 p1 = __floats2bfloat162_rn(o2, o3);
        uint2 u; u.x = *(uint32_t*)&p0; u.y = *(uint32_t*)&p1;
        *(uint2*)(op + c) = u;
    }
}

// ---------------------------------------------------------------------------
// Warp-per-row LayerNorm + ReLU + linear(384->1) + exp.
// ---------------------------------------------------------------------------
__global__ __launch_bounds__(256)
void ln_linear_exp(const float* __restrict__ in, const float* __restrict__ g,
                   const float* __restrict__ beta, const float* __restrict__ wl,
                   const float* __restrict__ bl, float* __restrict__ pred)
{
    const int row  = (blockIdx.x * 256 + threadIdx.x) >> 5;
    const int lane = threadIdx.x & 31;
    const float4* p = (const float4*)(in + (size_t)row * HH);

    float4 v[3];
    float s = 0.f, sq = 0.f;
#pragma unroll
    for (int i = 0; i < 3; i++) {
        v[i] = p[lane + 32 * i];
        s  += v[i].x + v[i].y + v[i].z + v[i].w;
        sq += v[i].x * v[i].x + v[i].y * v[i].y + v[i].z * v[i].z + v[i].w * v[i].w;
    }
#pragma unroll
    for (int off = 16; off > 0; off >>= 1) {
        s  += __shfl_xor_sync(0xffffffffu, s,  off);
        sq += __shfl_xor_sync(0xffffffffu, sq, off);
    }
    const float mu = s * (1.f / HH);
    const float rs = rsqrtf(sq * (1.f / HH) - mu * mu + 1e-5f);

    float d = 0.f;
#pragma unroll
    for (int i = 0; i < 3; i++) {
        const int c = (lane + 32 * i) * 4;
        const float4 gv = *(const float4*)(g + c);
        const float4 bv = *(const float4*)(beta + c);
        const float4 wv = *(const float4*)(wl + c);
        d += fmaxf(0.f, (v[i].x - mu) * rs * gv.x + bv.x) * wv.x;
        d += fmaxf(0.f, (v[i].y - mu) * rs * gv.y + bv.y) * wv.y;
        d += fmaxf(0.f, (v[i].z - mu) * rs * gv.z + bv.z) * wv.z;
        d += fmaxf(0.f, (v[i].w - mu) * rs * gv.w + bv.w) * wv.w;
    }
#pragma unroll
    for (int off = 16; off > 0; off >>= 1)
        d += __shfl_xor_sync(0xffffffffu, d, off);
    if (lane == 0) pred[row] = expf(d + bl[0]);
}

// ---------------------------------------------------------------------------
__global__ __launch_bounds__(256)
void f32_to_bf16(const float* __restrict__ x, __nv_bfloat16* __restrict__ y)
{
    const size_t i = ((size_t)blockIdx.x * 256 + threadIdx.x) * 4;
    float4 v = *(const float4*)(x + i);
    __nv_bfloat162 p0 = __floats2bfloat162_rn(v.x, v.y);
    __nv_bfloat162 p1 = __floats2bfloat162_rn(v.z, v.w);
    uint2 o;
    o.x = *(uint32_t*)&p0; o.y = *(uint32_t*)&p1;
    *(uint2*)(y + i) = o;
}

// Wt[n][kc] = W[kc][n], fp32 -> bf16. blockIdx.y selects weight set.
__global__ __launch_bounds__(256)
void wtrans2(const float* __restrict__ w1, __nv_bfloat16* __restrict__ wt1,
             const float* __restrict__ w2, __nv_bfloat16* __restrict__ wt2)
{
    const int id = blockIdx.x * 256 + threadIdx.x;   // HH*KDIM = 442368 exact
    const int n  = id / KDIM;
    const int kc = id - n * KDIM;
    if (blockIdx.y == 0) wt1[id] = __float2bfloat16(w1[(size_t)kc * HH + n]);
    else                 wt2[id] = __float2bfloat16(w2[(size_t)kc * HH + n]);
}

// ---------------------------------------------------------------------------
__global__ __launch_bounds__(1024)
void cumsum_kernel(const int* __restrict__ dur, int* __restrict__ cum)
{
    __shared__ int buf[SS];
    const int b = blockIdx.x, tid = threadIdx.x;
    buf[tid] = dur[b * SS + tid];
    __syncthreads();
#pragma unroll
    for (int off = 1; off < SS; off <<= 1) {
        int t = buf[tid];
        int u = (tid >= off) ? buf[tid - off] : 0;
        __syncthreads();
        buf[tid] = t + u;
        __syncthreads();
    }
    cum[b * SS + tid] = buf[tid];
}

__global__ __launch_bounds__(256)
void gather_kernel(const float* __restrict__ x, const int* __restrict__ cum,
                   float* __restrict__ out)
{
    const int gw   = (blockIdx.x * 256 + threadIdx.x) >> 5;
    const int lane = threadIdx.x & 31;
    const int b = gw / MAX_OUT_T;
    const int t = gw - b * MAX_OUT_T;

    const int* c = cum + b * SS;
    const bool valid = t < c[SS - 1];
    int lo = 0, hi = SS;
    while (lo < hi) {
        int mid = (lo + hi) >> 1;
        if (c[mid] <= t) lo = mid + 1; else hi = mid;
    }
    const int src = min(lo, SS - 1);

    const float4* xin = (const float4*)(x + ((size_t)b * SS + src) * CC);
    float4* o = (float4*)(out + (size_t)gw * CC);
    const float4 z = make_float4(0.f, 0.f, 0.f, 0.f);
#pragma unroll
    for (int i = 0; i < 3; i++)
        o[lane + i * 32] = valid ? xin[lane + i * 32] : z;
}

// ---------------------------------------------------------------------------
extern "C" void kernel_launch(void* const* d_in, const int* in_sizes, int n_in,
                              void* d_out, int out_size)
{
    const float* x     = (const float*)d_in[0];
    const int*   dur   = (const int*)  d_in[1];
    const float* w1    = (const float*)d_in[2];
    const float* b1    = (const float*)d_in[3];
    const float* g1    = (const float*)d_in[4];
    const float* beta1 = (const float*)d_in[5];
    const float* w2    = (const float*)d_in[6];
    const float* b2    = (const float*)d_in[7];
    const float* g2    = (const float*)d_in[8];
    const float* beta2 = (const float*)d_in[9];
    const float* wl    = (const float*)d_in[10];
    const float* bl    = (const float*)d_in[11];
    float* out = (float*)d_out;

    __nv_bfloat16 *xb, *h1b, *wt1, *wt2;
    float *tmp1, *tmp2; int* cum;
    cudaGetSymbolAddress((void**)&xb,   g_xb);
    cudaGetSymbolAddress((void**)&h1b,  g_h1b);
    cudaGetSymbolAddress((void**)&wt1,  g_wt1);
    cudaGetSymbolAddress((void**)&wt2,  g_wt2);
    cudaGetSymbolAddress((void**)&tmp1, g_tmp1);
    cudaGetSymbolAddress((void**)&tmp2, g_tmp2);
    cudaGetSymbolAddress((void**)&cum,  g_cum);

    cudaFuncSetAttribute(conv_gemm_mma, cudaFuncAttributeMaxDynamicSharedMemorySize, GEMM_SMEM);

    // side stream for the independent length-regulation branch (created once;
    // every call issues the identical launch DAG, so work stays deterministic)
    static cudaStream_t s2 = nullptr;
    static cudaEvent_t  ev_fork = nullptr, ev_join = nullptr;
    if (s2 == nullptr) {
        cudaStreamCreateWithFlags(&s2, cudaStreamNonBlocking);
        cudaEventCreateWithFlags(&ev_fork, cudaEventDisableTiming);
        cudaEventCreateWithFlags(&ev_join, cudaEventDisableTiming);
    }

    // ---- fork: length regulation on s2 (independent of predictor chain) ----
    cudaEventRecord(ev_fork, (cudaStream_t)0);
    cudaStreamWaitEvent(s2, ev_fork, 0);
    cumsum_kernel<<<BB, SS, 0, s2>>>(dur, cum);
    gather_kernel<<<(BB * MAX_OUT_T) / 8, 256, 0, s2>>>(x, cum, out);
    cudaEventRecord(ev_join, s2);

    // ---- predictor chain on the main stream --------------------------------
    f32_to_bf16<<<(M_TOTAL * CC) / 1024, 256>>>(x, xb);
    {
        dim3 wg((HH * KDIM) / 256, 2);
        wtrans2<<<wg, 256>>>(w1, wt1, w2, wt2);
    }

    dim3 gemm_grid(HH / 128, M_TOTAL / 128);   // (3, 256)
    conv_gemm_mma<<<gemm_grid, 256, GEMM_SMEM>>>(xb, wt1, b1, tmp1);
    ln_relu_bf16<<<M_TOTAL / 8, 256>>>(tmp1, g1, beta1, h1b);
    conv_gemm_mma<<<gemm_grid, 256, GEMM_SMEM>>>(h1b, wt2, b2, tmp2);
    ln_linear_exp<<<M_TOTAL / 8, 256>>>(tmp2, g2, beta2, wl, bl, out + PRED_OFFSET);

    // ---- join ---------------------------------------------------------------
    cudaStreamWaitEvent((cudaStream_t)0, ev_join, 0);
}